// round 15
// baseline (speedup 1.0000x reference)
#include <cuda_runtime.h>
#include <math.h>

// ACT_R activation recurrence — wavefront column sweep (R7 skeleton) with a
// lane-0-serial diagonal chain (no shfl on the critical path).
// sp: [S=512, B=256, 1] f32 (sorted along S).  w: [a, c, s, tau, h].
// out: [S-1, B, 1] f32.
//
//   E_i = sum_{j<i} max(sc_i - sc_j, 1)^{p_j},  p_j = -(c*E_j + a),  E_0 = 0
//   out[i-1] = sigmoid((log(E_i) - tau)/s)
//
// Diagonal redesign: within each warp's 32-row block, lane 0 runs the whole
// chain scalar-serially. It computes each row's last THREE terms itself
// (p_{r-1},p_{r-2},p_{r-3} are local registers -> serial step is just
// FMUL+ex2+FFMA ~= 24 cyc instead of shfl(26)+FMUL+ex2+FFMA ~= 50). Owner
// lanes accumulate columns <= row-4, receiving p via an off-chain broadcast
// shfl, and forward q = -(a + c*acc_partial) to lane 0 via an off-chain
// gather shfl two steps before it is needed. Near-diagonal lg2 values are
// precomputed (shfl_up) into smem; t3 uses an FMA-pipe poly to cap MUFU at
// 4 warp-instr/step. Row outputs recovered via E = -(p+a)/c.

#define S_LEN 512
#define BATCH 256

__device__ __forceinline__ float ex2f(float x) {
    float y; asm("ex2.approx.ftz.f32 %0, %1;" : "=f"(y) : "f"(x)); return y;
}
__device__ __forceinline__ float lg2f(float x) {
    float y; asm("lg2.approx.ftz.f32 %0, %1;" : "=f"(y) : "f"(x)); return y;
}
__device__ __forceinline__ float4 lds_v4_vol(const float* p) {
    float4 v; unsigned a = (unsigned)__cvta_generic_to_shared(p);
    asm volatile("ld.volatile.shared.v4.f32 {%0,%1,%2,%3}, [%4];"
                 : "=f"(v.x), "=f"(v.y), "=f"(v.z), "=f"(v.w) : "r"(a));
    return v;
}

// exp2(x) for x <= 0 on the FMA/ALU pipes (no MUFU). ~2e-6 rel err.
__device__ __forceinline__ float exp2_poly(float x) {
    x = fmaxf(x, -120.0f);
    float t  = x + 12582912.0f;                // 1.5*2^23 magic RN
    int   i  = __float_as_int(t);
    float xf = t - 12582912.0f;
    float r  = x - xf;                         // [-0.5, 0.5]
    float sc = __int_as_float((i - 0x4B3FFF81) << 23);
    float p  =          1.33335581e-3f;
    p = fmaf(p, r, 9.61812911e-3f);
    p = fmaf(p, r, 5.55041087e-2f);
    p = fmaf(p, r, 2.40226507e-1f);
    p = fmaf(p, r, 6.93147182e-1f);
    p = fmaf(p, r, 1.0f);
    return p * sc;
}

__global__ void __launch_bounds__(S_LEN, 2)
actr_kernel(const float* __restrict__ sp, const float* __restrict__ w,
            float* __restrict__ out) {
    __shared__ __align__(16) float sc[S_LEN];   // scaled timestamps
    __shared__ __align__(16) float psm[S_LEN];  // published p_j (NaN = not ready)
    __shared__ float l1s[S_LEN];                // lg2 d(t, t-1)
    __shared__ float l2s[S_LEN];                // lg2 d(t, t-2)
    __shared__ float l3s[S_LEN];                // lg2 d(t, t-3)

    const int b    = blockIdx.x;
    const int t    = threadIdx.x;          // owned row (natural order)
    const int lane = t & 31;
    const int base = t & ~31;

    const float a = w[0], c = w[1], s = w[2], tau = w[3], h = w[4];
    const float scale = 86400.0f * h;

    const float my_sc = sp[t * BATCH + b] * scale;
    sc[t]  = my_sc;
    psm[t] = __int_as_float(0x7fc00000);   // NaN sentinel

    // near-diagonal lg2 precompute (within-warp neighbors via shfl_up)
    float u1 = __shfl_up_sync(0xffffffffu, my_sc, 1);
    float u2 = __shfl_up_sync(0xffffffffu, my_sc, 2);
    float u3 = __shfl_up_sync(0xffffffffu, my_sc, 3);
    l1s[t] = (lane >= 1) ? lg2f(fmaxf(my_sc - u1, 1.f)) : 0.f;
    l2s[t] = (lane >= 2) ? lg2f(fmaxf(my_sc - u2, 1.f)) : 0.f;
    l3s[t] = (lane >= 3) ? lg2f(fmaxf(my_sc - u3, 1.f)) : 0.f;
    __syncthreads();

    volatile float* vp = psm;
    float accA = 0.f, accB = 0.f;

    // ---- off-diagonal columns j = 0 .. base-1 (R7: groups of 4) ----
    for (int j = 0; j < base; j += 4) {
        const float4 s4 = *reinterpret_cast<const float4*>(&sc[j]);
        float l0 = lg2f(fmaxf(my_sc - s4.x, 1.f));
        float l1 = lg2f(fmaxf(my_sc - s4.y, 1.f));
        float l2 = lg2f(fmaxf(my_sc - s4.z, 1.f));
        float l3 = lg2f(fmaxf(my_sc - s4.w, 1.f));
        float p3 = vp[j + 3];
        while (__isnanf(p3)) { __nanosleep(40); p3 = vp[j + 3]; }
        asm volatile("" ::: "memory");
        float4 p4 = lds_v4_vol(&psm[j]);
        accA += ex2f(p4.x * l0);  accB += ex2f(p4.y * l1);
        accA += ex2f(p4.z * l2);  accB += ex2f(p4.w * l3);
    }
    float acc_d = accA + accB;             // per-lane running sum (far so far)

    // ---- diagonal block: lane-0 serial chain, shfl traffic off-chain ----
    const float negc = -c, nega = -a;
    float qsnap = fmaf(negc, acc_d, nega); // q over cols consumed so far
    float p_cur = qsnap;                   // lane 0: p for row `base`
    if (lane == 0) vp[base] = p_cur;
    float pre  = __shfl_sync(0xffffffffu, qsnap, 1);  // pre[1]  (row base+1)
    float pre3 = __shfl_sync(0xffffffffu, qsnap, 2);  // pre3[2] (row base+2)
    float myp  = p_cur;                    // each lane's own published p

    #pragma unroll 1
    for (int r = 1; r < 32; ++r) {
        // broadcast p_{base+r-1} (off-chain for consumers)
        float bp = __shfl_sync(0xffffffffu, p_cur, 0);
        if (lane == r - 1) myp = bp;       // capture own p for epilogue
        // snapshot BEFORE this iteration's consume: covers cols <= base+r-2
        qsnap = fmaf(negc, acc_d, nega);
        int gs = (r + 2 < 32) ? (r + 2) : 31;
        float qg = __shfl_sync(0xffffffffu, qsnap, gs);  // q4 for row base+r+2
        // owners consume col base+r-1 (rows needing it outside near-band)
        if (lane >= r + 3) {
            float l = lg2f(fmaxf(my_sc - sc[base + r - 1], 1.f));
            acc_d += ex2f(bp * l);
        }
        // chain near-terms: all use lane0's local p_cur (= p_{base+r-1})
        int i2 = (r + 1 < 32) ? (base + r + 1) : (base + 31);
        int i3 = (r + 2 < 32) ? (base + r + 2) : (base + 31);
        float t1 = ex2f(p_cur * l1s[base + r]);   // serial: FMUL+ex2
        float t2 = ex2f(p_cur * l2s[i2]);         // off-chain (row base+r+1)
        float t3 = exp2_poly(p_cur * l3s[i3]);    // off-chain, FMA pipe
        float p_new = fmaf(negc, t1, pre);        // p_{base+r}   (chain FFMA)
        pre  = fmaf(negc, t2, pre3);              // pre[r+1]
        pre3 = fmaf(negc, t3, qg);                // pre3[r+2]
        if (lane == 0) vp[base + r] = p_new;      // publish for later warps
        p_cur = p_new;
    }
    {   // lane 31's p was never broadcast in-loop
        float bp = __shfl_sync(0xffffffffu, p_cur, 0);
        if (lane == 31) myp = bp;
    }

    // ---- epilogue: E = -(p + a)/c ;  sigmoid((log E - tau)/s) ----
    if (t >= 1) {
        const float LN2 = 0.69314718055994530942f;
        const float inv_sln2 = 1.0f / (s * LN2);
        float E = (myp + a) * __fdividef(-1.f, c);
        float m = lg2f(E) * LN2;
        float e = ex2f((tau - m) * inv_sln2);
        out[(t - 1) * BATCH + b] = __fdividef(1.f, 1.f + e);
    }
}

extern "C" void kernel_launch(void* const* d_in, const int* in_sizes, int n_in,
                              void* d_out, int out_size) {
    const float* sp = (const float*)d_in[0];
    const float* w  = (const float*)d_in[1];
    float* out      = (float*)d_out;
    (void)in_sizes; (void)n_in; (void)out_size;
    actr_kernel<<<BATCH, S_LEN>>>(sp, w, out);
}

// round 16
// speedup vs baseline: 1.6543x; 1.6543x over previous
#include <cuda_runtime.h>
#include <math.h>

// ACT_R activation recurrence — wavefront column sweep (R7 champion skeleton
// + hybrid poll backoff + lg2 double-buffering).
// sp: [S=512, B=256, 1] f32 (sorted along S).  w: [a, c, s, tau, h].
// out: [S-1, B, 1] f32.
//
//   E_i = sum_{j<i} max(sc_i - sc_j, 1)^{p_j},  p_j = -(c*E_j + a),  E_0 = 0
//   out[i-1] = sigmoid((log(E_i) - tau)/s)
//
// One block per batch element (grid=256), one thread per row (block=512),
// natural warp order (hi-wid = latest = arbiter priority). p_j published via
// NaN-sentinel smem; group-of-4 polling. Two micro-edits vs R7:
//  (1) polls within 64 columns of this warp's diagonal hot-spin (no
//      nanosleep) — wavefront handoff wake jitter off the chain;
//  (2) the NEXT group's sc load + lg2s are issued before polling the
//      current group, keeping MUFU lg2s in flight across the poll.

#define S_LEN 512
#define BATCH 256

__device__ __forceinline__ float ex2f(float x) {
    float y; asm("ex2.approx.ftz.f32 %0, %1;" : "=f"(y) : "f"(x)); return y;
}
__device__ __forceinline__ float lg2f(float x) {
    float y; asm("lg2.approx.ftz.f32 %0, %1;" : "=f"(y) : "f"(x)); return y;
}
__device__ __forceinline__ float4 lds_v4_vol(const float* p) {
    float4 v; unsigned a = (unsigned)__cvta_generic_to_shared(p);
    asm volatile("ld.volatile.shared.v4.f32 {%0,%1,%2,%3}, [%4];"
                 : "=f"(v.x), "=f"(v.y), "=f"(v.z), "=f"(v.w) : "r"(a));
    return v;
}

__global__ void __launch_bounds__(S_LEN, 2)
actr_kernel(const float* __restrict__ sp, const float* __restrict__ w,
            float* __restrict__ out) {
    __shared__ __align__(16) float sc[S_LEN];   // scaled timestamps
    __shared__ __align__(16) float psm[S_LEN];  // published p_j (NaN = not ready)

    const int b    = blockIdx.x;
    const int t    = threadIdx.x;          // owned row (natural order)
    const int lane = t & 31;
    const int base = t & ~31;              // this warp's diagonal base row

    const float a = w[0], c = w[1], s = w[2], tau = w[3], h = w[4];
    const float scale = 86400.0f * h;

    const float my_sc = sp[t * BATCH + b] * scale;
    sc[t]  = my_sc;
    psm[t] = __int_as_float(0x7fc00000);   // NaN sentinel
    __syncthreads();

    volatile float* vp = psm;
    float accA = 0.f, accB = 0.f;          // dual accumulators for FADD ILP

    // ---- off-diagonal columns j = 0 .. base-1, groups of 4, lg2 double-buffered ----
    const int hot_from = base - 64;        // hot-spin window near own diagonal
    float l0, l1, l2, l3;
    if (base > 0) {                        // prime group 0's lg2s
        const float4 s4 = *reinterpret_cast<const float4*>(&sc[0]);
        l0 = lg2f(fmaxf(my_sc - s4.x, 1.f));
        l1 = lg2f(fmaxf(my_sc - s4.y, 1.f));
        l2 = lg2f(fmaxf(my_sc - s4.z, 1.f));
        l3 = lg2f(fmaxf(my_sc - s4.w, 1.f));
    }
    for (int j = 0; j < base; j += 4) {
        // issue NEXT group's lg2s before this group's poll (MUFU stays busy)
        float n0, n1, n2, n3;
        if (j + 4 < base) {
            const float4 s4 = *reinterpret_cast<const float4*>(&sc[j + 4]);
            n0 = lg2f(fmaxf(my_sc - s4.x, 1.f));
            n1 = lg2f(fmaxf(my_sc - s4.y, 1.f));
            n2 = lg2f(fmaxf(my_sc - s4.z, 1.f));
            n3 = lg2f(fmaxf(my_sc - s4.w, 1.f));
        }
        // publishes are strictly in column order: once j+3 is ready, all are
        float p3 = vp[j + 3];
        if (j >= hot_from) {
            while (__isnanf(p3)) { p3 = vp[j + 3]; }               // hot spin
        } else {
            while (__isnanf(p3)) { __nanosleep(40); p3 = vp[j + 3]; }
        }
        asm volatile("" ::: "memory");     // keep group read below the poll
        float4 p4 = lds_v4_vol(&psm[j]);
        accA += ex2f(p4.x * l0);  accB += ex2f(p4.y * l1);
        accA += ex2f(p4.z * l2);  accB += ex2f(p4.w * l3);
        l0 = n0; l1 = n1; l2 = n2; l3 = n3;
    }
    float acc = accA + accB;

    // ---- diagonal block: serial chain via shfl (FFMA-shortened step) ----
    // q = -(c*acc + a) over columns accumulated so far (off-chain).
    // Lane k+1's publish value: p = q_prev + (-c)*term_k (one FFMA on chain).
    const float negc = -c;
    float q = -fmaf(c, acc, a);            // valid p for lane 0 (cols < base)
    float p_mine = q;
    #pragma unroll 1
    for (int k = 0; k < 31; ++k) {
        float l = lg2f(fmaxf(my_sc - sc[base + k], 1.f));  // off-chain
        if (lane == k) vp[base + k] = p_mine;  // publish for successor warps
        float pj = __shfl_sync(0xffffffffu, p_mine, k);
        float term = ex2f(pj * l);             // latency-critical: MUFU
        if (lane == k + 1) p_mine = fmaf(negc, term, q);   // fast-path publish
        if (lane > k) {
            acc += term;                   // off-chain bookkeeping
            q = -fmaf(c, acc, a);          // q for this lane's later fast-path
        }
    }
    if (lane == 31) vp[base + 31] = p_mine;   // last column for successor warps

    // ---- epilogue: sigmoid((m - tau)/s), m = log(E) ----
    if (t >= 1) {
        const float LN2 = 0.69314718055994530942f;
        const float inv_sln2 = 1.0f / (s * LN2);
        float m = lg2f(acc) * LN2;
        float e = ex2f((tau - m) * inv_sln2);
        out[(t - 1) * BATCH + b] = __fdividef(1.f, 1.f + e);
    }
}

extern "C" void kernel_launch(void* const* d_in, const int* in_sizes, int n_in,
                              void* d_out, int out_size) {
    const float* sp = (const float*)d_in[0];
    const float* w  = (const float*)d_in[1];
    float* out      = (float*)d_out;
    (void)in_sizes; (void)n_in; (void)out_size;
    actr_kernel<<<BATCH, S_LEN>>>(sp, w, out);
}